// round 1
// baseline (speedup 1.0000x reference)
#include <cuda_runtime.h>
#include <cuda_fp16.h>
#include <math.h>

#define N_NODES 100000
#define N_EDGES 2000000

// ---------------- scratch (static device globals; no allocation) ----------------
__device__ __align__(256) float  g_h[N_NODES * 64];     // node hidden state (fp32)
__device__ __align__(256) __half g_AB[N_NODES * 256];   // per node: A0|B0|A1|B1 (64 each, fp16)
__device__ __align__(256) float  g_acc[N_NODES * 128];  // per node: acc_e0|acc_e1 (fp32)
__device__ __align__(256) float  g_agg[N_NODES * 64];   // aggregated message after W2
__device__ __align__(256) float  g_gh[N_NODES * 192];   // h @ gru_wh + bh
__device__ __align__(256) int    g_cnt[N_NODES * 2];    // per (node, edge_type) in-degree

// ---------------- input projection: h = relu(LN(x@in_w + in_b)) ----------------
__global__ void k_input(const float* __restrict__ x, const float* __restrict__ in_w,
                        const float* __restrict__ in_b, const float* __restrict__ ln_g,
                        const float* __restrict__ ln_b) {
    int n = blockIdx.x * blockDim.x + threadIdx.x;
    if (n >= N_NODES) return;
    float x0 = x[n * 4 + 0], x1 = x[n * 4 + 1], x2 = x[n * 4 + 2], x3 = x[n * 4 + 3];
    float hb[64];
    float mean = 0.f;
#pragma unroll
    for (int j = 0; j < 64; j++) {
        float s = in_b[j] + x0 * in_w[j] + x1 * in_w[64 + j] + x2 * in_w[128 + j] + x3 * in_w[192 + j];
        hb[j] = s;
        mean += s;
    }
    mean *= (1.f / 64.f);
    float var = 0.f;
#pragma unroll
    for (int j = 0; j < 64; j++) {
        float d = hb[j] - mean;
        var += d * d;
    }
    var *= (1.f / 64.f);
    float inv = rsqrtf(var + 1e-5f);
#pragma unroll
    for (int j = 0; j < 64; j++) {
        float v = (hb[j] - mean) * inv * ln_g[j] + ln_b[j];
        g_h[n * 64 + j] = v > 0.f ? v : 0.f;
    }
    g_cnt[n * 2 + 0] = 0;
    g_cnt[n * 2 + 1] = 0;
}

// ---------------- per-(dst,type) edge counts (static graph: once per launch) ----
__global__ void k_cnt(const int* __restrict__ ei, const int* __restrict__ et) {
    int m = blockIdx.x * blockDim.x + threadIdx.x;
    if (m >= N_EDGES) return;
    int d = ei[N_EDGES + m];
    int e = et[m];
    atomicAdd(&g_cnt[d * 2 + e], 1);
}

// ---------------- generic fp32 GEMM core: 64-node tile, 256 threads ------------
// warp w handles nodes [w*8, w*8+8); lane j handles columns j + 32*c.
template <int K, int CPT>
__device__ __forceinline__ void gemm_core(const float* __restrict__ As,
                                          const float* __restrict__ Ws,
                                          float (&acc)[8][CPT], int w, int lane) {
    const int F = CPT * 32;
#pragma unroll 4
    for (int k = 0; k < K; k++) {
        float a[8];
#pragma unroll
        for (int i = 0; i < 8; i++) a[i] = As[(w * 8 + i) * K + k];
        float wv[CPT];
#pragma unroll
        for (int c = 0; c < CPT; c++) wv[c] = Ws[k * F + lane + 32 * c];
#pragma unroll
        for (int i = 0; i < 8; i++) {
#pragma unroll
            for (int c = 0; c < CPT; c++) acc[i][c] = fmaf(a[i], wv[c], acc[i][c]);
        }
    }
}

// ---------------- k_pre: AB = h @ [W1a0|W1b0|W1a1|W1b1] (+b1 on A), zero acc ----
__global__ __launch_bounds__(256) void k_pre(const float* __restrict__ w1,
                                             const float* __restrict__ b1, int l) {
    extern __shared__ float sm[];
    float* As = sm;                // 64*64
    float* Ws = sm + 64 * 64;      // 64*256
    __shared__ float bs[256];
    int tid = threadIdx.x, w = tid >> 5, lane = tid & 31;
    int base = blockIdx.x * 64;

    for (int idx = tid; idx < 64 * 256; idx += 256) {
        int k = idx >> 8, col = idx & 255;
        int e = col >> 7, part = (col >> 6) & 1, j = col & 63;
        int row = part ? (64 + k) : k;
        Ws[idx] = w1[((l * 2 + e) * 128 + row) * 64 + j];
    }
    {
        int col = tid;
        int e = col >> 7, part = (col >> 6) & 1, j = col & 63;
        bs[col] = part ? 0.f : b1[(l * 2 + e) * 64 + j];
    }
    for (int idx = tid; idx < 64 * 64; idx += 256) {
        int r = idx >> 6, k = idx & 63;
        int n = base + r;
        As[idx] = (n < N_NODES) ? g_h[n * 64 + k] : 0.f;
    }
    __syncthreads();

    float acc[8][8];
#pragma unroll
    for (int i = 0; i < 8; i++)
#pragma unroll
        for (int c = 0; c < 8; c++) acc[i][c] = 0.f;
    gemm_core<64, 8>(As, Ws, acc, w, lane);

#pragma unroll
    for (int i = 0; i < 8; i++) {
        int n = base + w * 8 + i;
        if (n >= N_NODES) continue;
#pragma unroll
        for (int c = 0; c < 8; c++) {
            int col = lane + 32 * c;
            float v = acc[i][c] + bs[col];
            g_AB[n * 256 + col] = __float2half(v);
            if (col < 128) g_acc[n * 128 + col] = 0.f;
        }
    }
}

// ---------------- k_edge: relu(A_e[src]+B_e[dst]) scattered into acc_e[dst] ----
__global__ __launch_bounds__(256) void k_edge(const int* __restrict__ ei,
                                              const int* __restrict__ et) {
    int gid = blockIdx.x * blockDim.x + threadIdx.x;
    int edge = gid >> 3;
    int t = gid & 7;  // 8 threads/edge, 8 features each
    if (edge >= N_EDGES) return;
    int s = ei[edge];
    int d = ei[N_EDGES + edge];
    int e = et[edge];

    const uint4* pa = reinterpret_cast<const uint4*>(g_AB + (size_t)s * 256 + e * 128) + t;
    const uint4* pb = reinterpret_cast<const uint4*>(g_AB + (size_t)d * 256 + e * 128 + 64) + t;
    uint4 ua = *pa;
    uint4 ub = *pb;
    const __half2* ha = reinterpret_cast<const __half2*>(&ua);
    const __half2* hb = reinterpret_cast<const __half2*>(&ub);

    float o[8];
#pragma unroll
    for (int q = 0; q < 4; q++) {
        float2 fa = __half22float2(ha[q]);
        float2 fb = __half22float2(hb[q]);
        float v0 = fa.x + fb.x;
        float v1 = fa.y + fb.y;
        o[2 * q + 0] = v0 > 0.f ? v0 : 0.f;
        o[2 * q + 1] = v1 > 0.f ? v1 : 0.f;
    }
    float* dstp = g_acc + (size_t)d * 128 + e * 64 + t * 8;
    asm volatile("red.global.add.v4.f32 [%0], {%1, %2, %3, %4};" ::"l"(dstp),
                 "f"(o[0]), "f"(o[1]), "f"(o[2]), "f"(o[3])
                 : "memory");
    asm volatile("red.global.add.v4.f32 [%0], {%1, %2, %3, %4};" ::"l"(dstp + 4),
                 "f"(o[4]), "f"(o[5]), "f"(o[6]), "f"(o[7])
                 : "memory");
}

// ---------------- k_agg: agg = acc @ [W2_0;W2_1] + cnt_e * b2_e ----------------
__global__ __launch_bounds__(256) void k_agg(const float* __restrict__ w2,
                                             const float* __restrict__ b2, int l) {
    extern __shared__ float sm[];
    float* As = sm;                 // 64*128
    float* Ws = sm + 64 * 128;      // 128*64
    __shared__ float b2s[128];
    int tid = threadIdx.x, w = tid >> 5, lane = tid & 31;
    int base = blockIdx.x * 64;

    for (int idx = tid; idx < 128 * 64; idx += 256) {
        int k = idx >> 6, j = idx & 63;
        int e = k >> 6, kk = k & 63;
        Ws[idx] = w2[((l * 2 + e) * 64 + kk) * 64 + j];
    }
    if (tid < 128) b2s[tid] = b2[(l * 2 + (tid >> 6)) * 64 + (tid & 63)];
    for (int idx = tid; idx < 64 * 128; idx += 256) {
        int r = idx >> 7, k = idx & 127;
        int n = base + r;
        As[idx] = (n < N_NODES) ? g_acc[n * 128 + k] : 0.f;
    }
    __syncthreads();

    float acc[8][2];
#pragma unroll
    for (int i = 0; i < 8; i++) { acc[i][0] = 0.f; acc[i][1] = 0.f; }
    gemm_core<128, 2>(As, Ws, acc, w, lane);

#pragma unroll
    for (int i = 0; i < 8; i++) {
        int n = base + w * 8 + i;
        if (n >= N_NODES) continue;
        float c0 = (float)g_cnt[n * 2 + 0];
        float c1 = (float)g_cnt[n * 2 + 1];
#pragma unroll
        for (int c = 0; c < 2; c++) {
            int col = lane + 32 * c;
            g_agg[n * 64 + col] = acc[i][c] + c0 * b2s[col] + c1 * b2s[64 + col];
        }
    }
}

// ---------------- k_gh: gh = h @ gru_wh[l] + bh ---------------------------------
__global__ __launch_bounds__(256) void k_gh(const float* __restrict__ wh,
                                            const float* __restrict__ bh, int l) {
    extern __shared__ float sm[];
    float* As = sm;                // 64*64
    float* Ws = sm + 64 * 64;      // 64*192
    __shared__ float bhs[192];
    int tid = threadIdx.x, w = tid >> 5, lane = tid & 31;
    int base = blockIdx.x * 64;

    for (int idx = tid; idx < 64 * 192; idx += 256) Ws[idx] = wh[l * 64 * 192 + idx];
    if (tid < 192) bhs[tid] = bh[l * 192 + tid];
    for (int idx = tid; idx < 64 * 64; idx += 256) {
        int r = idx >> 6, k = idx & 63;
        int n = base + r;
        As[idx] = (n < N_NODES) ? g_h[n * 64 + k] : 0.f;
    }
    __syncthreads();

    float acc[8][6];
#pragma unroll
    for (int i = 0; i < 8; i++)
#pragma unroll
        for (int c = 0; c < 6; c++) acc[i][c] = 0.f;
    gemm_core<64, 6>(As, Ws, acc, w, lane);

#pragma unroll
    for (int i = 0; i < 8; i++) {
        int n = base + w * 8 + i;
        if (n >= N_NODES) continue;
#pragma unroll
        for (int c = 0; c < 6; c++) {
            int col = lane + 32 * c;
            g_gh[n * 192 + col] = acc[i][c] + bhs[col];
        }
    }
}

// ---------------- k_gi_gru: gi = agg @ gru_wi[l] + bi, then GRU update ----------
__global__ __launch_bounds__(256) void k_gi_gru(const float* __restrict__ wi,
                                                const float* __restrict__ bi, int l) {
    extern __shared__ float sm[];
    float* As = sm;                // 64*64 (agg)
    float* Ws = sm + 64 * 64;      // 64*192
    __shared__ float bis[192];
    int tid = threadIdx.x, w = tid >> 5, lane = tid & 31;
    int base = blockIdx.x * 64;

    for (int idx = tid; idx < 64 * 192; idx += 256) Ws[idx] = wi[l * 64 * 192 + idx];
    if (tid < 192) bis[tid] = bi[l * 192 + tid];
    for (int idx = tid; idx < 64 * 64; idx += 256) {
        int r = idx >> 6, k = idx & 63;
        int n = base + r;
        As[idx] = (n < N_NODES) ? g_agg[n * 64 + k] : 0.f;
    }
    __syncthreads();

    float acc[8][6];
#pragma unroll
    for (int i = 0; i < 8; i++)
#pragma unroll
        for (int c = 0; c < 6; c++) acc[i][c] = 0.f;
    gemm_core<64, 6>(As, Ws, acc, w, lane);

    // columns owned by lane j: j(+32) -> r, j+64(+32) -> z, j+128(+32) -> n
#pragma unroll
    for (int i = 0; i < 8; i++) {
        int n = base + w * 8 + i;
        if (n >= N_NODES) continue;
        float v[6], g[6];
#pragma unroll
        for (int c = 0; c < 6; c++) {
            int col = lane + 32 * c;
            v[c] = acc[i][c] + bis[col];
            g[c] = g_gh[n * 192 + col];
        }
#pragma unroll
        for (int p = 0; p < 2; p++) {
            int j = lane + 32 * p;
            float r = 1.f / (1.f + expf(-(v[p] + g[p])));
            float z = 1.f / (1.f + expf(-(v[2 + p] + g[2 + p])));
            float nn = tanhf(v[4 + p] + r * g[4 + p]);
            float ho = g_h[n * 64 + j];
            g_h[n * 64 + j] = (1.f - z) * nn + z * ho;
        }
    }
}

// ---------------- k_ro: out = relu(h@ro_w1+b1)@ro_w2+b2; corr write -------------
__global__ __launch_bounds__(256) void k_ro(const float* __restrict__ w1,
                                            const float* __restrict__ b1,
                                            const float* __restrict__ w2,
                                            const float* __restrict__ b2,
                                            const int* __restrict__ node_type,
                                            const float* __restrict__ x,
                                            float* __restrict__ out) {
    extern __shared__ float sm[];
    float* As = sm;               // 64*64
    float* Ws = sm + 64 * 64;     // 64*64
    __shared__ float b1s[64];
    __shared__ float w2s[64];
    int tid = threadIdx.x, w = tid >> 5, lane = tid & 31;
    int base = blockIdx.x * 64;

    for (int idx = tid; idx < 64 * 64; idx += 256) Ws[idx] = w1[idx];
    if (tid < 64) { b1s[tid] = b1[tid]; w2s[tid] = w2[tid]; }
    for (int idx = tid; idx < 64 * 64; idx += 256) {
        int r = idx >> 6, k = idx & 63;
        int n = base + r;
        As[idx] = (n < N_NODES) ? g_h[n * 64 + k] : 0.f;
    }
    __syncthreads();

    float acc[8][2];
#pragma unroll
    for (int i = 0; i < 8; i++) { acc[i][0] = 0.f; acc[i][1] = 0.f; }
    gemm_core<64, 2>(As, Ws, acc, w, lane);

    float b2v = b2[0];
#pragma unroll
    for (int i = 0; i < 8; i++) {
        int n = base + w * 8 + i;
        float t0 = acc[i][0] + b1s[lane];
        float t1 = acc[i][1] + b1s[lane + 32];
        t0 = t0 > 0.f ? t0 : 0.f;
        t1 = t1 > 0.f ? t1 : 0.f;
        float p = t0 * w2s[lane] + t1 * w2s[lane + 32];
#pragma unroll
        for (int off = 16; off > 0; off >>= 1) p += __shfl_xor_sync(0xffffffffu, p, off);
        if (lane == 0 && n < N_NODES) {
            float o = p + b2v;
            out[n] = (node_type[n] == 0) ? (x[n * 4] + o) : 0.f;
        }
    }
}

// ---------------- launch ---------------------------------------------------------
extern "C" void kernel_launch(void* const* d_in, const int* in_sizes, int n_in,
                              void* d_out, int out_size) {
    const float* x        = (const float*)d_in[0];
    const int*   node_ty  = (const int*)d_in[1];
    const int*   ei       = (const int*)d_in[2];
    const int*   et       = (const int*)d_in[3];
    const float* in_w     = (const float*)d_in[4];
    const float* in_b     = (const float*)d_in[5];
    const float* ln_g     = (const float*)d_in[6];
    const float* ln_b     = (const float*)d_in[7];
    const float* mlp_w1   = (const float*)d_in[8];
    const float* mlp_b1   = (const float*)d_in[9];
    const float* mlp_w2   = (const float*)d_in[10];
    const float* mlp_b2   = (const float*)d_in[11];
    const float* gru_wi   = (const float*)d_in[12];
    const float* gru_wh   = (const float*)d_in[13];
    const float* gru_bi   = (const float*)d_in[14];
    const float* gru_bh   = (const float*)d_in[15];
    const float* ro_w1    = (const float*)d_in[16];
    const float* ro_b1    = (const float*)d_in[17];
    const float* ro_w2    = (const float*)d_in[18];
    const float* ro_b2    = (const float*)d_in[19];
    float* out = (float*)d_out;

    cudaFuncSetAttribute(k_pre,    cudaFuncAttributeMaxDynamicSharedMemorySize, 96 * 1024);
    cudaFuncSetAttribute(k_agg,    cudaFuncAttributeMaxDynamicSharedMemorySize, 96 * 1024);
    cudaFuncSetAttribute(k_gh,     cudaFuncAttributeMaxDynamicSharedMemorySize, 96 * 1024);
    cudaFuncSetAttribute(k_gi_gru, cudaFuncAttributeMaxDynamicSharedMemorySize, 96 * 1024);
    cudaFuncSetAttribute(k_ro,     cudaFuncAttributeMaxDynamicSharedMemorySize, 96 * 1024);

    const int NB = (N_NODES + 63) / 64;

    k_input<<<(N_NODES + 127) / 128, 128>>>(x, in_w, in_b, ln_g, ln_b);
    k_cnt<<<(N_EDGES + 255) / 256, 256>>>(ei, et);

    for (int l = 0; l < 3; l++) {
        k_pre<<<NB, 256, (64 * 64 + 64 * 256) * 4>>>(mlp_w1, mlp_b1, l);
        k_edge<<<(N_EDGES * 8 + 255) / 256, 256>>>(ei, et);
        k_agg<<<NB, 256, (64 * 128 + 128 * 64) * 4>>>(mlp_w2, mlp_b2, l);
        k_gh<<<NB, 256, (64 * 64 + 64 * 192) * 4>>>(gru_wh, gru_bh, l);
        k_gi_gru<<<NB, 256, (64 * 64 + 64 * 192) * 4>>>(gru_wi, gru_bi, l);
    }
    k_ro<<<NB, 256, (64 * 64 + 64 * 64) * 4>>>(ro_w1, ro_b1, ro_w2, ro_b2, node_ty, x, out);
}